// round 2
// baseline (speedup 1.0000x reference)
#include <cuda_runtime.h>
#include <cuda_bf16.h>
#include <math.h>

// Problem constants
#define Nn 4
#define Cc 64
#define Hh 128
#define Ww 128
#define HW (Hh*Ww)           // 16384
#define Kk 9
#define COUT 64
#define CK (Cc*Kk)           // 576
#define OFFCH 18
#define MASKCH 9

// Scratch (device globals -- allocation-free per harness rules)
__device__ float g_off [Nn*OFFCH*HW];    // offsets, layout [n][18][pq]
__device__ float g_mask[Nn*MASKCH*HW];   // sigmoid(mask), layout [n][9][pq]
__device__ float g_cols[(size_t)Nn*CK*HW]; // im2col of deformed samples [n][c*9+k][pq]

// ---------------------------------------------------------------------------
// Kernel A: 3x3 conv, 64 -> 27 channels, pad 1, stride 1. Writes offsets and
// sigmoid(mask) to scratch. Tile: 16x16 pixels, 128 threads, 2 px/thread.
// ---------------------------------------------------------------------------
__global__ __launch_bounds__(128) void convA_kernel(
    const float* __restrict__ x,
    const float* __restrict__ w_om,
    const float* __restrict__ b_om)
{
    const int n  = blockIdx.z;
    const int p0 = blockIdx.y * 16;
    const int q0 = blockIdx.x * 16;
    const int tid = threadIdx.x;            // 0..127
    const int tr  = tid >> 3;               // 0..15 (row in tile)
    const int tc  = (tid & 7) * 2;          // 0,2,..,14 (col pair)
    const int p = p0 + tr;
    const int q = q0 + tc;

    __shared__ float wsm[32 * 27 * 9];      // 31104 B: one 32-channel chunk of weights

    float acc0[27], acc1[27];
#pragma unroll
    for (int o = 0; o < 27; o++) { acc0[o] = 0.f; acc1[o] = 0.f; }

    const float* xn = x + (size_t)n * Cc * HW;

    for (int cc = 0; cc < 2; cc++) {        // channel chunks of 32
        __syncthreads();
        for (int idx = tid; idx < 32 * 243; idx += 128) {
            int cl  = idx / 243;
            int rem = idx - cl * 243;       // o*9+k
            int o = rem / 9, k = rem - o * 9;
            wsm[cl * 243 + rem] = w_om[((size_t)o * Cc + cc * 32 + cl) * 9 + k];
        }
        __syncthreads();

        for (int cl = 0; cl < 32; cl++) {
            const float* xp = xn + (cc * 32 + cl) * HW;
            float tap[3][4];
#pragma unroll
            for (int di = 0; di < 3; di++) {
                int yy = p - 1 + di;
#pragma unroll
                for (int dj = 0; dj < 4; dj++) {
                    int xx = q - 1 + dj;
                    bool ok = (yy >= 0) & (yy < Hh) & (xx >= 0) & (xx < Ww);
                    tap[di][dj] = ok ? __ldg(xp + yy * Ww + xx) : 0.f;
                }
            }
            const float* wp = &wsm[cl * 243];
#pragma unroll
            for (int o = 0; o < 27; o++) {
#pragma unroll
                for (int di = 0; di < 3; di++) {
#pragma unroll
                    for (int dj = 0; dj < 3; dj++) {
                        float w = wp[o * 9 + di * 3 + dj];
                        acc0[o] = fmaf(w, tap[di][dj],     acc0[o]);
                        acc1[o] = fmaf(w, tap[di][dj + 1], acc1[o]);
                    }
                }
            }
        }
    }

    const int pq = p * Ww + q;
#pragma unroll
    for (int o = 0; o < 27; o++) {
        float b  = __ldg(b_om + o);
        float v0 = acc0[o] + b;
        float v1 = acc1[o] + b;
        if (o < OFFCH) {
            g_off[((size_t)n * OFFCH + o) * HW + pq]     = v0;
            g_off[((size_t)n * OFFCH + o) * HW + pq + 1] = v1;
        } else {
            int m = o - OFFCH;
            g_mask[((size_t)n * MASKCH + m) * HW + pq]     = 1.f / (1.f + expf(-v0));
            g_mask[((size_t)n * MASKCH + m) * HW + pq + 1] = 1.f / (1.f + expf(-v1));
        }
    }
}

// ---------------------------------------------------------------------------
// Kernel B: deformable bilinear sampling -> im2col columns * mask.
// One thread per (n, k, pq), loops over 64 channels.
// ---------------------------------------------------------------------------
__global__ __launch_bounds__(256) void sampleB_kernel(const float* __restrict__ x)
{
    int gid = blockIdx.x * blockDim.x + threadIdx.x;
    const int total = Nn * Kk * HW;
    if (gid >= total) return;

    const int pq = gid & (HW - 1);
    const int k  = (gid >> 14) % Kk;
    const int n  = gid / (Kk * HW);
    const int p  = pq >> 7;
    const int q  = pq & (Ww - 1);

    const float offy = g_off[((size_t)n * OFFCH + 2 * k)     * HW + pq];
    const float offx = g_off[((size_t)n * OFFCH + 2 * k + 1) * HW + pq];
    const float msk  = g_mask[((size_t)n * MASKCH + k) * HW + pq];

    const float y  = (float)(p - 1 + k / 3) + offy;
    const float xs = (float)(q - 1 + k % 3) + offx;

    const float y0f = floorf(y), x0f = floorf(xs);
    const float wy1 = y - y0f,   wx1 = xs - x0f;
    const int   y0 = (int)y0f,   x0 = (int)x0f;
    const int   y1 = y0 + 1,     x1 = x0 + 1;

    float w00 = (1.f - wy1) * (1.f - wx1);
    float w01 = (1.f - wy1) * wx1;
    float w10 = wy1 * (1.f - wx1);
    float w11 = wy1 * wx1;

    const bool vy0 = (y0 >= 0) & (y0 < Hh);
    const bool vy1 = (y1 >= 0) & (y1 < Hh);
    const bool vx0 = (x0 >= 0) & (x0 < Ww);
    const bool vx1 = (x1 >= 0) & (x1 < Ww);
    if (!(vy0 & vx0)) w00 = 0.f;
    if (!(vy0 & vx1)) w01 = 0.f;
    if (!(vy1 & vx0)) w10 = 0.f;
    if (!(vy1 & vx1)) w11 = 0.f;

    const int y0c = min(max(y0, 0), Hh - 1);
    const int y1c = min(max(y1, 0), Hh - 1);
    const int x0c = min(max(x0, 0), Ww - 1);
    const int x1c = min(max(x1, 0), Ww - 1);

    const int i00 = y0c * Ww + x0c;
    const int i01 = y0c * Ww + x1c;
    const int i10 = y1c * Ww + x0c;
    const int i11 = y1c * Ww + x1c;

    const float* xp = x + (size_t)n * Cc * HW;
    float* outp = g_cols + ((size_t)n * CK + k) * HW + pq;  // stride per c: 9*HW

#pragma unroll 4
    for (int c = 0; c < Cc; c++) {
        const float* b = xp + c * HW;
        float v = w00 * __ldg(b + i00) + w01 * __ldg(b + i01)
                + w10 * __ldg(b + i10) + w11 * __ldg(b + i11);
        outp[(size_t)c * Kk * HW] = v * msk;
    }
}

// ---------------------------------------------------------------------------
// Kernel C: per-image GEMM  out[o][pq] = sum_ck W[o][ck] * cols[ck][pq]
// M=64, N=16384, K=576. Block tile 64x128, 256 threads, 4x8 per thread.
// ---------------------------------------------------------------------------
__global__ __launch_bounds__(256) void gemmC_kernel(
    const float* __restrict__ w_dcn,
    float* __restrict__ out)
{
    const int n  = blockIdx.z;
    const int j0 = blockIdx.x * 128;
    const int tid = threadIdx.x;

    __shared__ float As[16][64];     // [kk][m]
    __shared__ float Bs[16][128];    // [kk][j]

    const int m0 = (tid >> 4) * 4;   // 0..60
    const int jt = (tid & 15) * 8;   // 0..120

    float acc[4][8];
#pragma unroll
    for (int i = 0; i < 4; i++)
#pragma unroll
        for (int j = 0; j < 8; j++) acc[i][j] = 0.f;

    const float* Bg = g_cols + (size_t)n * CK * HW + j0;

    for (int k0 = 0; k0 < CK; k0 += 16) {
        // load A: 16x64
        for (int idx = tid; idx < 1024; idx += 256) {
            int kk = idx >> 6, m = idx & 63;
            As[kk][m] = __ldg(w_dcn + (size_t)m * CK + k0 + kk);
        }
        // load B: 16x128 (coalesced rows)
        for (int idx = tid; idx < 2048; idx += 256) {
            int kk = idx >> 7, j = idx & 127;
            Bs[kk][j] = Bg[(size_t)(k0 + kk) * HW + j];
        }
        __syncthreads();
#pragma unroll
        for (int kk = 0; kk < 16; kk++) {
            float a[4], b[8];
            float4 av = *(const float4*)&As[kk][m0];
            a[0] = av.x; a[1] = av.y; a[2] = av.z; a[3] = av.w;
            float4 bv0 = *(const float4*)&Bs[kk][jt];
            float4 bv1 = *(const float4*)&Bs[kk][jt + 4];
            b[0]=bv0.x; b[1]=bv0.y; b[2]=bv0.z; b[3]=bv0.w;
            b[4]=bv1.x; b[5]=bv1.y; b[6]=bv1.z; b[7]=bv1.w;
#pragma unroll
            for (int i = 0; i < 4; i++)
#pragma unroll
                for (int j = 0; j < 8; j++)
                    acc[i][j] = fmaf(a[i], b[j], acc[i][j]);
        }
        __syncthreads();
    }

    float* op = out + (size_t)n * COUT * HW + j0;
#pragma unroll
    for (int i = 0; i < 4; i++) {
        float4 v0 = make_float4(acc[i][0], acc[i][1], acc[i][2], acc[i][3]);
        float4 v1 = make_float4(acc[i][4], acc[i][5], acc[i][6], acc[i][7]);
        *(float4*)(op + (size_t)(m0 + i) * HW + jt)     = v0;
        *(float4*)(op + (size_t)(m0 + i) * HW + jt + 4) = v1;
    }
}

// ---------------------------------------------------------------------------
extern "C" void kernel_launch(void* const* d_in, const int* in_sizes, int n_in,
                              void* d_out, int out_size)
{
    const float* x     = (const float*)d_in[0];  // (4,64,128,128)
    const float* w_om  = (const float*)d_in[1];  // (27,64,3,3)
    const float* b_om  = (const float*)d_in[2];  // (27,)
    const float* w_dcn = (const float*)d_in[3];  // (64,64,3,3)
    float* out = (float*)d_out;                  // (4,64,128,128)

    dim3 gA(Ww / 16, Hh / 16, Nn);               // 8 x 8 x 4
    convA_kernel<<<gA, 128>>>(x, w_om, b_om);

    int totalB = Nn * Kk * HW;                   // 589824
    sampleB_kernel<<<(totalB + 255) / 256, 256>>>(x);

    dim3 gC(HW / 128, 1, Nn);                    // 128 x 1 x 4
    gemmC_kernel<<<gC, 256>>>(w_dcn, out);
}

// round 3
// speedup vs baseline: 1.0663x; 1.0663x over previous
#include <cuda_runtime.h>
#include <cuda_bf16.h>
#include <math.h>

// Problem constants
#define Nn 4
#define Cc 64
#define Hh 128
#define Ww 128
#define HW (Hh*Ww)           // 16384
#define Kk 9
#define COUT 64
#define CK (Cc*Kk)           // 576
#define OFFCH 18
#define MASKCH 9

// Scratch (device globals -- allocation-free per harness rules)
__device__ float g_off [Nn*OFFCH*HW];    // offsets, layout [n][18][pq]
__device__ float g_mask[Nn*MASKCH*HW];   // sigmoid(mask), layout [n][9][pq]

// ---------------------------------------------------------------------------
// Kernel A: 3x3 conv, 64 -> 27 ch. Tile 16x8 px, 256 threads, 2 threads/px
// (each handles 32 input channels, shfl-combined). 512 blocks -> fills chip.
// ---------------------------------------------------------------------------
__global__ __launch_bounds__(256) void convA_kernel(
    const float* __restrict__ x,
    const float* __restrict__ w_om,
    const float* __restrict__ b_om)
{
    const int n  = blockIdx.z;
    const int p0 = blockIdx.y * 8;
    const int q0 = blockIdx.x * 16;
    const int tid  = threadIdx.x;          // 0..255
    const int h    = tid & 1;              // channel half
    const int pxid = tid >> 1;             // 0..127
    const int p = p0 + (pxid >> 4);
    const int q = q0 + (pxid & 15);

    __shared__ float wsm[32 * 243];        // one 32-channel chunk of weights

    float acc[27];
#pragma unroll
    for (int o = 0; o < 27; o++) acc[o] = 0.f;

    // boundary predicates, invariant over channels
    bool rv[3], cv[3];
#pragma unroll
    for (int d = 0; d < 3; d++) {
        rv[d] = (unsigned)(p - 1 + d) < (unsigned)Hh;
        cv[d] = (unsigned)(q - 1 + d) < (unsigned)Ww;
    }
    const int base = (p - 1) * Ww + (q - 1);

    for (int cc = 0; cc < 2; cc++) {       // channel chunks of 32
        __syncthreads();
        for (int idx = tid; idx < 32 * 243; idx += 256) {
            int cl  = idx / 243;
            int rem = idx - cl * 243;      // o*9+k
            int o = rem / 9, k = rem - o * 9;
            wsm[idx] = w_om[((size_t)o * Cc + cc * 32 + cl) * 9 + k];
        }
        __syncthreads();

#pragma unroll 2
        for (int i = 0; i < 16; i++) {
            const int cl = h * 16 + i;
            const float* xp = x + ((size_t)n * Cc + cc * 32 + cl) * HW;
            float tap[9];
#pragma unroll
            for (int di = 0; di < 3; di++)
#pragma unroll
                for (int dj = 0; dj < 3; dj++) {
                    bool ok = rv[di] & cv[dj];
                    tap[di * 3 + dj] = ok ? __ldg(xp + base + di * Ww + dj) : 0.f;
                }
            const float* wp = &wsm[cl * 243];
#pragma unroll
            for (int o = 0; o < 27; o++) {
#pragma unroll
                for (int t = 0; t < 9; t++)
                    acc[o] = fmaf(wp[o * 9 + t], tap[t], acc[o]);
            }
        }
    }

    // combine the two channel halves (lanes tid, tid^1 are in the same warp)
#pragma unroll
    for (int o = 0; o < 27; o++)
        acc[o] += __shfl_xor_sync(0xFFFFFFFFu, acc[o], 1);

    if (h == 0) {
        const int pq = p * Ww + q;
#pragma unroll
        for (int o = 0; o < 27; o++) {
            float v = acc[o] + __ldg(b_om + o);
            if (o < OFFCH) {
                g_off[((size_t)n * OFFCH + o) * HW + pq] = v;
            } else {
                g_mask[((size_t)n * MASKCH + (o - OFFCH)) * HW + pq] =
                    1.f / (1.f + expf(-v));
            }
        }
    }
}

// ---------------------------------------------------------------------------
// Kernel BC (fused): per 128-pixel tile, compute bilinear descriptors once,
// then GEMM over c with on-the-fly gathered B tiles. No im2col scratch.
// out[o][pq] = sum_{c,k} w_dcn[o][c*9+k] * sample(c,k,pq)*mask(k,pq)
// ---------------------------------------------------------------------------
__global__ __launch_bounds__(256) void fusedBC_kernel(
    const float* __restrict__ x,
    const float* __restrict__ w_dcn,
    float* __restrict__ out)
{
    const int n  = blockIdx.z;
    const int j0 = blockIdx.x * 128;
    const int tid = threadIdx.x;

    __shared__ int4   sIdx[Kk * 128];      // 4 corner indices per (k,j)
    __shared__ float4 sW  [Kk * 128];      // 4 mask-premultiplied weights
    __shared__ float  Asub[Kk * 64];       // w_dcn slice for current c: [k][m]
    __shared__ float  Bs  [Kk * 128];      // sampled tile: [k][j]

    // ---- Phase 1: sampling descriptors ----
    for (int e = tid; e < Kk * 128; e += 256) {
        const int k  = e >> 7;
        const int j  = e & 127;
        const int pq = j0 + j;
        const int p  = pq >> 7;
        const int q  = pq & (Ww - 1);

        const float offy = g_off[((size_t)n * OFFCH + 2 * k)     * HW + pq];
        const float offx = g_off[((size_t)n * OFFCH + 2 * k + 1) * HW + pq];
        const float msk  = g_mask[((size_t)n * MASKCH + k) * HW + pq];

        const float y  = (float)(p - 1 + k / 3) + offy;
        const float xs = (float)(q - 1 + k % 3) + offx;

        const float y0f = floorf(y), x0f = floorf(xs);
        const float wy1 = y - y0f,   wx1 = xs - x0f;
        const int   y0 = (int)y0f,   x0 = (int)x0f;
        const int   y1 = y0 + 1,     x1 = x0 + 1;

        float w00 = (1.f - wy1) * (1.f - wx1) * msk;
        float w01 = (1.f - wy1) * wx1 * msk;
        float w10 = wy1 * (1.f - wx1) * msk;
        float w11 = wy1 * wx1 * msk;

        const bool vy0 = (unsigned)y0 < (unsigned)Hh;
        const bool vy1 = (unsigned)y1 < (unsigned)Hh;
        const bool vx0 = (unsigned)x0 < (unsigned)Ww;
        const bool vx1 = (unsigned)x1 < (unsigned)Ww;
        if (!(vy0 & vx0)) w00 = 0.f;
        if (!(vy0 & vx1)) w01 = 0.f;
        if (!(vy1 & vx0)) w10 = 0.f;
        if (!(vy1 & vx1)) w11 = 0.f;

        const int y0c = min(max(y0, 0), Hh - 1);
        const int y1c = min(max(y1, 0), Hh - 1);
        const int x0c = min(max(x0, 0), Ww - 1);
        const int x1c = min(max(x1, 0), Ww - 1);

        sIdx[e] = make_int4(y0c * Ww + x0c, y0c * Ww + x1c,
                            y1c * Ww + x0c, y1c * Ww + x1c);
        sW[e]   = make_float4(w00, w01, w10, w11);
    }
    __syncthreads();

    // ---- Phase 2: GEMM over channels with on-the-fly B tiles ----
    const int m0 = (tid >> 4) * 4;   // out-channel group
    const int jt = (tid & 15) * 8;   // pixel group

    float acc[4][8];
#pragma unroll
    for (int i = 0; i < 4; i++)
#pragma unroll
        for (int j = 0; j < 8; j++) acc[i][j] = 0.f;

    const float* xn = x + (size_t)n * Cc * HW;

    for (int c = 0; c < Cc; c++) {
        // stage A slice: Asub[k][m] = w_dcn[m][c*9+k]
        for (int idx = tid; idx < Kk * 64; idx += 256) {
            int m = idx / 9, k = idx - m * 9;
            Asub[k * 64 + m] = __ldg(w_dcn + (size_t)m * CK + c * Kk + k);
        }
        // build B tile by gathering
        const float* xp = xn + c * HW;
        for (int e = tid; e < Kk * 128; e += 256) {
            const int4   ii = sIdx[e];
            const float4 ww = sW[e];
            float v = ww.x * __ldg(xp + ii.x) + ww.y * __ldg(xp + ii.y)
                    + ww.z * __ldg(xp + ii.z) + ww.w * __ldg(xp + ii.w);
            Bs[e] = v;
        }
        __syncthreads();

#pragma unroll
        for (int k = 0; k < Kk; k++) {
            float4 av = *(const float4*)&Asub[k * 64 + m0];
            float4 b0 = *(const float4*)&Bs[k * 128 + jt];
            float4 b1 = *(const float4*)&Bs[k * 128 + jt + 4];
            float a[4] = {av.x, av.y, av.z, av.w};
            float b[8] = {b0.x, b0.y, b0.z, b0.w, b1.x, b1.y, b1.z, b1.w};
#pragma unroll
            for (int i = 0; i < 4; i++)
#pragma unroll
                for (int j = 0; j < 8; j++)
                    acc[i][j] = fmaf(a[i], b[j], acc[i][j]);
        }
        __syncthreads();
    }

    float* op = out + (size_t)n * COUT * HW + j0;
#pragma unroll
    for (int i = 0; i < 4; i++) {
        float4 v0 = make_float4(acc[i][0], acc[i][1], acc[i][2], acc[i][3]);
        float4 v1 = make_float4(acc[i][4], acc[i][5], acc[i][6], acc[i][7]);
        *(float4*)(op + (size_t)(m0 + i) * HW + jt)     = v0;
        *(float4*)(op + (size_t)(m0 + i) * HW + jt + 4) = v1;
    }
}

// ---------------------------------------------------------------------------
extern "C" void kernel_launch(void* const* d_in, const int* in_sizes, int n_in,
                              void* d_out, int out_size)
{
    const float* x     = (const float*)d_in[0];  // (4,64,128,128)
    const float* w_om  = (const float*)d_in[1];  // (27,64,3,3)
    const float* b_om  = (const float*)d_in[2];  // (27,)
    const float* w_dcn = (const float*)d_in[3];  // (64,64,3,3)
    float* out = (float*)d_out;                  // (4,64,128,128)

    dim3 gA(Ww / 16, Hh / 8, Nn);                // 8 x 16 x 4 = 512 blocks
    convA_kernel<<<gA, 256>>>(x, w_om, b_om);

    dim3 gBC(HW / 128, 1, Nn);                   // 128 x 1 x 4 = 512 blocks
    fusedBC_kernel<<<gBC, 256>>>(x, w_dcn, out);
}

// round 5
// speedup vs baseline: 2.2530x; 2.1130x over previous
#include <cuda_runtime.h>
#include <cuda_bf16.h>
#include <math.h>
#include <cstdint>

// Problem constants
#define Nn 4
#define Cc 64
#define Hh 128
#define Ww 128
#define HW (Hh*Ww)           // 16384
#define Kk 9
#define COUT 64
#define CK (Cc*Kk)           // 576
#define OFFCH 18
#define MASKCH 9

// Scratch (device globals -- allocation-free per harness rules)
__device__ float g_off [Nn*OFFCH*HW];    // offsets, layout [n][18][pq]
__device__ float g_mask[Nn*MASKCH*HW];   // sigmoid(mask), layout [n][9][pq]

// ---------------------------------------------------------------------------
// Warp-MMA helpers (sm_80+ PTX: assembles for target sm_100)
// ---------------------------------------------------------------------------
__device__ __forceinline__ uint32_t smem_u32(const void* p) {
    uint32_t a;
    asm("{ .reg .u64 t; cvta.to.shared.u64 t, %1; cvt.u32.u64 %0, t; }"
        : "=r"(a) : "l"(p));
    return a;
}
__device__ __forceinline__ void ldsm_x4(uint32_t* r, uint32_t addr) {
    asm volatile("ldmatrix.sync.aligned.m8n8.x4.shared.b16 {%0,%1,%2,%3}, [%4];"
        : "=r"(r[0]), "=r"(r[1]), "=r"(r[2]), "=r"(r[3]) : "r"(addr));
}
__device__ __forceinline__ void mma_bf16(float* c, const uint32_t* a, const uint32_t* b) {
    asm volatile(
        "mma.sync.aligned.m16n8k16.row.col.f32.bf16.bf16.f32 "
        "{%0,%1,%2,%3}, {%4,%5,%6,%7}, {%8,%9}, {%0,%1,%2,%3};"
        : "+f"(c[0]), "+f"(c[1]), "+f"(c[2]), "+f"(c[3])
        : "r"(a[0]), "r"(a[1]), "r"(a[2]), "r"(a[3]), "r"(b[0]), "r"(b[1]));
}

// SMEM layout (dynamic). Row pitch 144B = 128B data + 16B skew:
// ldmatrix row-starts rotate 1 bank-group per row -> conflict-free LDSM.
#define PITCH 144
#define SM_SHI 0                      // 128 rows * 144
#define SM_SLO (SM_SHI + 128*PITCH)   // 18432
#define SM_WHI (SM_SLO + 128*PITCH)   // 64 rows * 144
#define SM_WLO (SM_WHI + 64*PITCH)
#define SM_IDX (SM_WLO + 64*PITCH)    // int4[1152]
#define SM_WGT (SM_IDX + 18432)       // float4[1152]
#define SM_TOTAL (SM_WGT + 18432)     // 92160 bytes

// ---------------------------------------------------------------------------
// Kernel A: 3x3 conv, 64 -> 27 ch. (unchanged from round 3 -- measured ~89us)
// ---------------------------------------------------------------------------
__global__ __launch_bounds__(256) void convA_kernel(
    const float* __restrict__ x,
    const float* __restrict__ w_om,
    const float* __restrict__ b_om)
{
    const int n  = blockIdx.z;
    const int p0 = blockIdx.y * 8;
    const int q0 = blockIdx.x * 16;
    const int tid  = threadIdx.x;
    const int h    = tid & 1;
    const int pxid = tid >> 1;
    const int p = p0 + (pxid >> 4);
    const int q = q0 + (pxid & 15);

    __shared__ float wsm[32 * 243];

    float acc[27];
#pragma unroll
    for (int o = 0; o < 27; o++) acc[o] = 0.f;

    bool rv[3], cv[3];
#pragma unroll
    for (int d = 0; d < 3; d++) {
        rv[d] = (unsigned)(p - 1 + d) < (unsigned)Hh;
        cv[d] = (unsigned)(q - 1 + d) < (unsigned)Ww;
    }
    const int base = (p - 1) * Ww + (q - 1);

    for (int cc = 0; cc < 2; cc++) {
        __syncthreads();
        for (int idx = tid; idx < 32 * 243; idx += 256) {
            int cl  = idx / 243;
            int rem = idx - cl * 243;
            int o = rem / 9, k = rem - o * 9;
            wsm[idx] = w_om[((size_t)o * Cc + cc * 32 + cl) * 9 + k];
        }
        __syncthreads();

#pragma unroll 2
        for (int i = 0; i < 16; i++) {
            const int cl = h * 16 + i;
            const float* xp = x + ((size_t)n * Cc + cc * 32 + cl) * HW;
            float tap[9];
#pragma unroll
            for (int di = 0; di < 3; di++)
#pragma unroll
                for (int dj = 0; dj < 3; dj++) {
                    bool ok = rv[di] & cv[dj];
                    tap[di * 3 + dj] = ok ? __ldg(xp + base + di * Ww + dj) : 0.f;
                }
            const float* wp = &wsm[cl * 243];
#pragma unroll
            for (int o = 0; o < 27; o++) {
#pragma unroll
                for (int t = 0; t < 9; t++)
                    acc[o] = fmaf(wp[o * 9 + t], tap[t], acc[o]);
            }
        }
    }

#pragma unroll
    for (int o = 0; o < 27; o++)
        acc[o] += __shfl_xor_sync(0xFFFFFFFFu, acc[o], 1);

    if (h == 0) {
        const int pq = p * Ww + q;
#pragma unroll
        for (int o = 0; o < 27; o++) {
            float v = acc[o] + __ldg(b_om + o);
            if (o < OFFCH) {
                g_off[((size_t)n * OFFCH + o) * HW + pq] = v;
            } else {
                g_mask[((size_t)n * MASKCH + (o - OFFCH)) * HW + pq] =
                    1.f / (1.f + expf(-v));
            }
        }
    }
}

// ---------------------------------------------------------------------------
// Kernel BC: fused deform-sample + GEMM on HMMA (mma.sync, bf16 3-term split)
//   D[128px, 64o] = S[128,576] x W[64,576]^T  per 128-pixel tile.
// ---------------------------------------------------------------------------
__global__ __launch_bounds__(256, 2) void fusedBC_mma_kernel(
    const float* __restrict__ x,
    const float* __restrict__ w_dcn,
    float* __restrict__ out)
{
    extern __shared__ char smem[];
    const uint32_t sbase = smem_u32(smem);
    const int n   = blockIdx.z;
    const int j0  = blockIdx.x * 128;     // one full image row of pixels
    const int tid = threadIdx.x;
    const int wid = tid >> 5;
    const int lid = tid & 31;

    int4*   sIdx = (int4*)  (smem + SM_IDX);
    float4* sW   = (float4*)(smem + SM_WGT);

    // ---- Phase 1: sampling descriptors for 9*128 (k, pixel) pairs ----
    for (int e = tid; e < Kk * 128; e += 256) {
        const int k  = e >> 7;
        const int j  = e & 127;
        const int pq = j0 + j;
        const int p  = pq >> 7;
        const int q  = pq & (Ww - 1);

        const float offy = g_off[((size_t)n * OFFCH + 2 * k)     * HW + pq];
        const float offx = g_off[((size_t)n * OFFCH + 2 * k + 1) * HW + pq];
        const float msk  = g_mask[((size_t)n * MASKCH + k) * HW + pq];

        const float y  = (float)(p - 1 + k / 3) + offy;
        const float xs = (float)(q - 1 + k % 3) + offx;

        const float y0f = floorf(y), x0f = floorf(xs);
        const float wy1 = y - y0f,   wx1 = xs - x0f;
        const int   y0 = (int)y0f,   x0 = (int)x0f;
        const int   y1 = y0 + 1,     x1 = x0 + 1;

        float w00 = (1.f - wy1) * (1.f - wx1) * msk;
        float w01 = (1.f - wy1) * wx1 * msk;
        float w10 = wy1 * (1.f - wx1) * msk;
        float w11 = wy1 * wx1 * msk;

        const bool vy0 = (unsigned)y0 < (unsigned)Hh;
        const bool vy1 = (unsigned)y1 < (unsigned)Hh;
        const bool vx0 = (unsigned)x0 < (unsigned)Ww;
        const bool vx1 = (unsigned)x1 < (unsigned)Ww;
        if (!(vy0 & vx0)) w00 = 0.f;
        if (!(vy0 & vx1)) w01 = 0.f;
        if (!(vy1 & vx0)) w10 = 0.f;
        if (!(vy1 & vx1)) w11 = 0.f;

        const int y0c = min(max(y0, 0), Hh - 1);
        const int y1c = min(max(y1, 0), Hh - 1);
        const int x0c = min(max(x0, 0), Ww - 1);
        const int x1c = min(max(x1, 0), Ww - 1);

        sIdx[e] = make_int4(y0c * Ww + x0c, y0c * Ww + x1c,
                            y1c * Ww + x0c, y1c * Ww + x1c);
        sW[e]   = make_float4(w00, w01, w10, w11);
    }
    __syncthreads();

    const float* xn = x + (size_t)n * Cc * HW;

    float acc[8][4];
#pragma unroll
    for (int t = 0; t < 8; t++)
#pragma unroll
        for (int i = 0; i < 4; i++) acc[t][i] = 0.f;

    // per-thread ldmatrix address components (tile = lid>>3, r = lid&7)
    const int a_row  = wid * 16 + (((lid >> 3) & 1) << 3) + (lid & 7);
    const int a_cg   = (lid >> 4);               // +k0/8
    const int b_oofs = ((lid >> 4) << 3) + (lid & 7);
    const int b_cg   = ((lid >> 3) & 1);         // +k0/8

    // ---- Phase 2: 9 K-chunks of 64 ----
    for (int j = 0; j < 9; j++) {
        __syncthreads();   // previous chunk's ldmatrix reads done

        // Gather S chunk: pairs (row = pixel, cg = colk/2). Lanes span pixels
        // of one image row -> corner loads nearly contiguous.
        for (int e = tid; e < 4096; e += 256) {
            const int row = e & 127;
            const int cg  = e >> 7;            // 0..31
            uint32_t hi2 = 0, lo2 = 0;
#pragma unroll
            for (int s = 0; s < 2; s++) {
                const int ck = j * 64 + cg * 2 + s;
                const int c  = ck / 9;
                const int k  = ck - c * 9;
                const int4   ii = sIdx[k * 128 + row];
                const float4 wv = sW[k * 128 + row];
                const float* xp = xn + c * HW;
                float v = wv.x * __ldg(xp + ii.x) + wv.y * __ldg(xp + ii.y)
                        + wv.z * __ldg(xp + ii.z) + wv.w * __ldg(xp + ii.w);
                uint32_t hb = __bfloat16_as_ushort(__float2bfloat16(v));
                float vhi = __bfloat162float(__float2bfloat16(v));
                uint32_t lb = __bfloat16_as_ushort(__float2bfloat16(v - vhi));
                hi2 |= hb << (16 * s);
                lo2 |= lb << (16 * s);
            }
            const uint32_t off = row * PITCH + cg * 4;
            *(uint32_t*)(smem + SM_SHI + off) = hi2;
            *(uint32_t*)(smem + SM_SLO + off) = lo2;
        }
        // Stage W chunk: (o = e>>5, cg = e&31) -> coalesced loads & stores
        for (int e = tid; e < 2048; e += 256) {
            const int o  = e >> 5;
            const int cg = e & 31;
            const float2 wv = *(const float2*)(w_dcn + (size_t)o * CK + j * 64 + cg * 2);
            uint32_t h0 = __bfloat16_as_ushort(__float2bfloat16(wv.x));
            float h0f = __bfloat162float(__float2bfloat16(wv.x));
            uint32_t l0 = __bfloat16_as_ushort(__float2bfloat16(wv.x - h0f));
            uint32_t h1 = __bfloat16_as_ushort(__float2bfloat16(wv.y));
            float h1f = __bfloat162float(__float2bfloat16(wv.y));
            uint32_t l1 = __bfloat16_as_ushort(__float2bfloat16(wv.y - h1f));
            const uint32_t off = o * PITCH + cg * 4;
            *(uint32_t*)(smem + SM_WHI + off) = h0 | (h1 << 16);
            *(uint32_t*)(smem + SM_WLO + off) = l0 | (l1 << 16);
        }
        __syncthreads();

        // 4 k16 steps
#pragma unroll
        for (int ks = 0; ks < 4; ks++) {
            uint32_t ahi[4], alo[4];
            const uint32_t aoff = a_row * PITCH + (ks * 2 + a_cg) * 16;
            ldsm_x4(ahi, sbase + SM_SHI + aoff);
            ldsm_x4(alo, sbase + SM_SLO + aoff);
#pragma unroll
            for (int nt = 0; nt < 4; nt++) {
                uint32_t bh[4], bl[4];
                const uint32_t boff = (nt * 16 + b_oofs) * PITCH + (ks * 2 + b_cg) * 16;
                ldsm_x4(bh, sbase + SM_WHI + boff);
                ldsm_x4(bl, sbase + SM_WLO + boff);
                mma_bf16(acc[nt * 2],     ahi, bh);
                mma_bf16(acc[nt * 2 + 1], ahi, bh + 2);
                mma_bf16(acc[nt * 2],     ahi, bl);
                mma_bf16(acc[nt * 2 + 1], ahi, bl + 2);
                mma_bf16(acc[nt * 2],     alo, bh);
                mma_bf16(acc[nt * 2 + 1], alo, bh + 2);
            }
        }
    }

    // ---- Epilogue: D fragment -> out[n][o][pq] ----
    const int px = j0 + wid * 16 + (lid >> 2);
#pragma unroll
    for (int t = 0; t < 8; t++) {
        const int o0 = t * 8 + 2 * (lid & 3);
        float* op = out + (size_t)n * COUT * HW;
        op[(size_t)o0       * HW + px    ] = acc[t][0];
        op[(size_t)(o0 + 1) * HW + px    ] = acc[t][1];
        op[(size_t)o0       * HW + px + 8] = acc[t][2];
        op[(size_t)(o0 + 1) * HW + px + 8] = acc[t][3];
    }
}

// ---------------------------------------------------------------------------
extern "C" void kernel_launch(void* const* d_in, const int* in_sizes, int n_in,
                              void* d_out, int out_size)
{
    const float* x     = (const float*)d_in[0];  // (4,64,128,128)
    const float* w_om  = (const float*)d_in[1];  // (27,64,3,3)
    const float* b_om  = (const float*)d_in[2];  // (27,)
    const float* w_dcn = (const float*)d_in[3];  // (64,64,3,3)
    float* out = (float*)d_out;                  // (4,64,128,128)

    dim3 gA(Ww / 16, Hh / 8, Nn);                // 512 blocks
    convA_kernel<<<gA, 256>>>(x, w_om, b_om);

    cudaFuncSetAttribute(fusedBC_mma_kernel,
                         cudaFuncAttributeMaxDynamicSharedMemorySize, SM_TOTAL);
    dim3 gBC(HW / 128, 1, Nn);                   // 512 blocks
    fusedBC_mma_kernel<<<gBC, 256, SM_TOTAL>>>(x, w_dcn, out);
}

// round 6
// speedup vs baseline: 2.5740x; 1.1424x over previous
#include <cuda_runtime.h>
#include <cuda_bf16.h>
#include <math.h>
#include <cstdint>

// Problem constants
#define Nn 4
#define Cc 64
#define Hh 128
#define Ww 128
#define HW (Hh*Ww)           // 16384
#define Kk 9
#define COUT 64
#define CK (Cc*Kk)           // 576
#define OFFCH 18
#define MASKCH 9

// Scratch (device globals -- allocation-free per harness rules)
__device__ float g_off [Nn*OFFCH*HW];        // offsets [n][18][pq]
__device__ float g_mask[Nn*MASKCH*HW];       // sigmoid(mask) [n][9][pq]
__device__ unsigned short g_whi[Kk*COUT*Cc]; // w_dcn k-major bf16 hi [k][o][c]
__device__ unsigned short g_wlo[Kk*COUT*Cc]; // w_dcn k-major bf16 lo [k][o][c]

// ---------------------------------------------------------------------------
// Warp-MMA helpers (sm_80+ PTX: assembles for target sm_100)
// ---------------------------------------------------------------------------
__device__ __forceinline__ uint32_t smem_u32(const void* p) {
    uint32_t a;
    asm("{ .reg .u64 t; cvta.to.shared.u64 t, %1; cvt.u32.u64 %0, t; }"
        : "=r"(a) : "l"(p));
    return a;
}
__device__ __forceinline__ void ldsm_x4(uint32_t* r, uint32_t addr) {
    asm volatile("ldmatrix.sync.aligned.m8n8.x4.shared.b16 {%0,%1,%2,%3}, [%4];"
        : "=r"(r[0]), "=r"(r[1]), "=r"(r[2]), "=r"(r[3]) : "r"(addr));
}
__device__ __forceinline__ void mma_bf16(float* c, const uint32_t* a, const uint32_t* b) {
    asm volatile(
        "mma.sync.aligned.m16n8k16.row.col.f32.bf16.bf16.f32 "
        "{%0,%1,%2,%3}, {%4,%5,%6,%7}, {%8,%9}, {%0,%1,%2,%3};"
        : "+f"(c[0]), "+f"(c[1]), "+f"(c[2]), "+f"(c[3])
        : "r"(a[0]), "r"(a[1]), "r"(a[2]), "r"(a[3]), "r"(b[0]), "r"(b[1]));
}

// SMEM layout. Row pitch 144B = 128B data + 16B skew (conflict-free LDSM).
#define PITCH 144
#define SM_DI  0                        // int4[128]   = 2048
#define SM_DW  (SM_DI + 2048)           // float4[128] = 2048
#define SM_SHI (SM_DW + 2048)           // 128*144 = 18432
#define SM_SLO (SM_SHI + 128*PITCH)
#define SM_WHI (SM_SLO + 128*PITCH)     // 64*144 = 9216
#define SM_WLO (SM_WHI + 64*PITCH)
#define SM_TOTAL (SM_WLO + 64*PITCH)    // 59392 bytes -> 3 CTAs/SM

// ---------------------------------------------------------------------------
// Kernel W-prep: reorder w_dcn to k-major bf16 hi/lo: g_w*[k][o][c]
// ---------------------------------------------------------------------------
__global__ __launch_bounds__(256) void wprep_kernel(const float* __restrict__ w_dcn)
{
    const int e = blockIdx.x * 256 + threadIdx.x;
    if (e >= Kk * COUT * Cc) return;
    const int k = e / (COUT * Cc);
    const int r = e - k * (COUT * Cc);
    const int o = r >> 6;
    const int c = r & 63;
    const float w = __ldg(w_dcn + (size_t)o * CK + c * Kk + k);
    const __nv_bfloat16 hi = __float2bfloat16(w);
    const __nv_bfloat16 lo = __float2bfloat16(w - __bfloat162float(hi));
    g_whi[e] = __bfloat16_as_ushort(hi);
    g_wlo[e] = __bfloat16_as_ushort(lo);
}

// ---------------------------------------------------------------------------
// Kernel A: 3x3 conv, 64 -> 27 ch. (unchanged -- measured ~79us)
// ---------------------------------------------------------------------------
__global__ __launch_bounds__(256) void convA_kernel(
    const float* __restrict__ x,
    const float* __restrict__ w_om,
    const float* __restrict__ b_om)
{
    const int n  = blockIdx.z;
    const int p0 = blockIdx.y * 8;
    const int q0 = blockIdx.x * 16;
    const int tid  = threadIdx.x;
    const int h    = tid & 1;
    const int pxid = tid >> 1;
    const int p = p0 + (pxid >> 4);
    const int q = q0 + (pxid & 15);

    __shared__ float wsm[32 * 243];

    float acc[27];
#pragma unroll
    for (int o = 0; o < 27; o++) acc[o] = 0.f;

    bool rv[3], cv[3];
#pragma unroll
    for (int d = 0; d < 3; d++) {
        rv[d] = (unsigned)(p - 1 + d) < (unsigned)Hh;
        cv[d] = (unsigned)(q - 1 + d) < (unsigned)Ww;
    }
    const int base = (p - 1) * Ww + (q - 1);

    for (int cc = 0; cc < 2; cc++) {
        __syncthreads();
        for (int idx = tid; idx < 32 * 243; idx += 256) {
            int cl  = idx / 243;
            int rem = idx - cl * 243;
            int o = rem / 9, k = rem - o * 9;
            wsm[idx] = w_om[((size_t)o * Cc + cc * 32 + cl) * 9 + k];
        }
        __syncthreads();

#pragma unroll 2
        for (int i = 0; i < 16; i++) {
            const int cl = h * 16 + i;
            const float* xp = x + ((size_t)n * Cc + cc * 32 + cl) * HW;
            float tap[9];
#pragma unroll
            for (int di = 0; di < 3; di++)
#pragma unroll
                for (int dj = 0; dj < 3; dj++) {
                    bool ok = rv[di] & cv[dj];
                    tap[di * 3 + dj] = ok ? __ldg(xp + base + di * Ww + dj) : 0.f;
                }
            const float* wp = &wsm[cl * 243];
#pragma unroll
            for (int o = 0; o < 27; o++) {
#pragma unroll
                for (int t = 0; t < 9; t++)
                    acc[o] = fmaf(wp[o * 9 + t], tap[t], acc[o]);
            }
        }
    }

#pragma unroll
    for (int o = 0; o < 27; o++)
        acc[o] += __shfl_xor_sync(0xFFFFFFFFu, acc[o], 1);

    if (h == 0) {
        const int pq = p * Ww + q;
#pragma unroll
        for (int o = 0; o < 27; o++) {
            float v = acc[o] + __ldg(b_om + o);
            if (o < OFFCH) {
                g_off[((size_t)n * OFFCH + o) * HW + pq] = v;
            } else {
                g_mask[((size_t)n * MASKCH + (o - OFFCH)) * HW + pq] =
                    1.f / (1.f + expf(-v));
            }
        }
    }
}

// ---------------------------------------------------------------------------
// Kernel BC: fused deform-sample + HMMA GEMM, K-major chunks (k=j per chunk).
//   D[128px, 64o] = S[128,576'] x W'[64,576']^T, ck' = k*64 + c.
// ---------------------------------------------------------------------------
__global__ __launch_bounds__(256, 3) void fusedBC_mma_kernel(
    const float* __restrict__ x,
    float* __restrict__ out)
{
    extern __shared__ char smem[];
    const uint32_t sbase = smem_u32(smem);
    const int n   = blockIdx.z;
    const int j0  = blockIdx.x * 128;     // one full image row of pixels
    const int tid = threadIdx.x;
    const int wid = tid >> 5;
    const int lid = tid & 31;

    int4*   sDI = (int4*)  (smem + SM_DI);
    float4* sDW = (float4*)(smem + SM_DW);

    const float* xn = x + (size_t)n * Cc * HW;

    float acc[8][4];
#pragma unroll
    for (int t = 0; t < 8; t++)
#pragma unroll
        for (int i = 0; i < 4; i++) acc[t][i] = 0.f;

    // ldmatrix address components
    const int a_row  = wid * 16 + (((lid >> 3) & 1) << 3) + (lid & 7);
    const int a_cg   = (lid >> 4);               // +k0/8
    const int b_oofs = ((lid >> 4) << 3) + (lid & 7);
    const int b_cg   = ((lid >> 3) & 1);         // +k0/8

    const int g_row  = tid & 127;                // gather row (pixel)
    const int g_half = tid >> 7;                 // channel half

    // ---- 9 chunks, chunk j = kernel tap k=j, K-slice = 64 channels ----
    for (int j = 0; j < 9; j++) {
        __syncthreads();   // prev chunk's ldsm reads + desc reads done

        if (tid < 128) {
            // 128 sampling descriptors for (k=j, row)
            const int row = tid;
            const int pq  = j0 + row;
            const int p   = pq >> 7;
            const int q   = pq & (Ww - 1);

            const float offy = g_off[((size_t)n * OFFCH + 2 * j)     * HW + pq];
            const float offx = g_off[((size_t)n * OFFCH + 2 * j + 1) * HW + pq];
            const float msk  = g_mask[((size_t)n * MASKCH + j) * HW + pq];

            const float y  = (float)(p - 1 + j / 3) + offy;
            const float xs = (float)(q - 1 + j % 3) + offx;

            const float y0f = floorf(y), x0f = floorf(xs);
            const float wy1 = y - y0f,   wx1 = xs - x0f;
            const int   y0 = (int)y0f,   x0 = (int)x0f;
            const int   y1 = y0 + 1,     x1 = x0 + 1;

            float w00 = (1.f - wy1) * (1.f - wx1) * msk;
            float w01 = (1.f - wy1) * wx1 * msk;
            float w10 = wy1 * (1.f - wx1) * msk;
            float w11 = wy1 * wx1 * msk;

            if (!(((unsigned)y0 < (unsigned)Hh) & ((unsigned)x0 < (unsigned)Ww))) w00 = 0.f;
            if (!(((unsigned)y0 < (unsigned)Hh) & ((unsigned)x1 < (unsigned)Ww))) w01 = 0.f;
            if (!(((unsigned)y1 < (unsigned)Hh) & ((unsigned)x0 < (unsigned)Ww))) w10 = 0.f;
            if (!(((unsigned)y1 < (unsigned)Hh) & ((unsigned)x1 < (unsigned)Ww))) w11 = 0.f;

            const int y0c = min(max(y0, 0), Hh - 1);
            const int y1c = min(max(y1, 0), Hh - 1);
            const int x0c = min(max(x0, 0), Ww - 1);
            const int x1c = min(max(x1, 0), Ww - 1);

            sDI[row] = make_int4(y0c * Ww + x0c, y0c * Ww + x1c,
                                 y1c * Ww + x0c, y1c * Ww + x1c);
            sDW[row] = make_float4(w00, w01, w10, w11);
        } else {
            // Stage W chunk (preconverted, k-major, coalesced): 2048 u32 each
            const uint32_t* whp = (const uint32_t*)g_whi + j * 2048;
            const uint32_t* wlp = (const uint32_t*)g_wlo + j * 2048;
#pragma unroll 4
            for (int i = 0; i < 16; i++) {
                const int e  = (tid - 128) + i * 128;   // 0..2047
                const int o  = e >> 5;
                const int cg = e & 31;
                const uint32_t off = o * PITCH + cg * 4;
                *(uint32_t*)(smem + SM_WHI + off) = __ldg(whp + e);
                *(uint32_t*)(smem + SM_WLO + off) = __ldg(wlp + e);
            }
        }
        __syncthreads();

        // Gather S chunk: thread owns (row, 16 channel-pairs). Descriptor
        // loaded ONCE; channel walk is pointer += 2*HW.
        {
            const int4   ii = sDI[g_row];
            const float4 wv = sDW[g_row];
            const float* p00 = xn + ii.x + (size_t)g_half * 32 * HW;
            const float* p01 = xn + ii.y + (size_t)g_half * 32 * HW;
            const float* p10 = xn + ii.z + (size_t)g_half * 32 * HW;
            const float* p11 = xn + ii.w + (size_t)g_half * 32 * HW;
            uint32_t soff = g_row * PITCH + (g_half * 16) * 4;
#pragma unroll
            for (int i = 0; i < 16; i++) {
                float v0 = wv.x * __ldg(p00)      + wv.y * __ldg(p01)
                         + wv.z * __ldg(p10)      + wv.w * __ldg(p11);
                float v1 = wv.x * __ldg(p00 + HW) + wv.y * __ldg(p01 + HW)
                         + wv.z * __ldg(p10 + HW) + wv.w * __ldg(p11 + HW);
                p00 += 2 * HW; p01 += 2 * HW; p10 += 2 * HW; p11 += 2 * HW;

                const __nv_bfloat16 h0 = __float2bfloat16(v0);
                const __nv_bfloat16 h1 = __float2bfloat16(v1);
                const uint32_t l0 = __bfloat16_as_ushort(
                    __float2bfloat16(v0 - __bfloat162float(h0)));
                const uint32_t l1 = __bfloat16_as_ushort(
                    __float2bfloat16(v1 - __bfloat162float(h1)));
                *(uint32_t*)(smem + SM_SHI + soff) =
                    (uint32_t)__bfloat16_as_ushort(h0) |
                    ((uint32_t)__bfloat16_as_ushort(h1) << 16);
                *(uint32_t*)(smem + SM_SLO + soff) = l0 | (l1 << 16);
                soff += 4;
            }
        }
        __syncthreads();

        // 4 k16 steps x 4 n-tiles x 3 split terms
#pragma unroll
        for (int ks = 0; ks < 4; ks++) {
            uint32_t ahi[4], alo[4];
            const uint32_t aoff = a_row * PITCH + (ks * 2 + a_cg) * 16;
            ldsm_x4(ahi, sbase + SM_SHI + aoff);
            ldsm_x4(alo, sbase + SM_SLO + aoff);
#pragma unroll
            for (int nt = 0; nt < 4; nt++) {
                uint32_t bh[4], bl[4];
                const uint32_t boff = (nt * 16 + b_oofs) * PITCH + (ks * 2 + b_cg) * 16;
                ldsm_x4(bh, sbase + SM_WHI + boff);
                ldsm_x4(bl, sbase + SM_WLO + boff);
                mma_bf16(acc[nt * 2],     ahi, bh);
                mma_bf16(acc[nt * 2 + 1], ahi, bh + 2);
                mma_bf16(acc[nt * 2],     ahi, bl);
                mma_bf16(acc[nt * 2 + 1], ahi, bl + 2);
                mma_bf16(acc[nt * 2],     alo, bh);
                mma_bf16(acc[nt * 2 + 1], alo, bh + 2);
            }
        }
    }

    // ---- Epilogue: D fragment -> out[n][o][pq] ----
    const int px = j0 + wid * 16 + (lid >> 2);
    float* op = out + (size_t)n * COUT * HW;
#pragma unroll
    for (int t = 0; t < 8; t++) {
        const int o0 = t * 8 + 2 * (lid & 3);
        op[(size_t)o0       * HW + px    ] = acc[t][0];
        op[(size_t)(o0 + 1) * HW + px    ] = acc[t][1];
        op[(size_t)o0       * HW + px + 8] = acc[t][2];
        op[(size_t)(o0 + 1) * HW + px + 8] = acc[t][3];
    }
}

// ---------------------------------------------------------------------------
extern "C" void kernel_launch(void* const* d_in, const int* in_sizes, int n_in,
                              void* d_out, int out_size)
{
    const float* x     = (const float*)d_in[0];  // (4,64,128,128)
    const float* w_om  = (const float*)d_in[1];  // (27,64,3,3)
    const float* b_om  = (const float*)d_in[2];  // (27,)
    const float* w_dcn = (const float*)d_in[3];  // (64,64,3,3)
    float* out = (float*)d_out;                  // (4,64,128,128)

    wprep_kernel<<<(Kk * COUT * Cc + 255) / 256, 256>>>(w_dcn);

    dim3 gA(Ww / 16, Hh / 8, Nn);                // 512 blocks
    convA_kernel<<<gA, 256>>>(x, w_om, b_om);

    cudaFuncSetAttribute(fusedBC_mma_kernel,
                         cudaFuncAttributeMaxDynamicSharedMemorySize, SM_TOTAL);
    dim3 gBC(HW / 128, 1, Nn);                   // 512 blocks
    fusedBC_mma_kernel<<<gBC, 256, SM_TOTAL>>>(x, out);
}

// round 7
// speedup vs baseline: 3.2504x; 1.2628x over previous
#include <cuda_runtime.h>
#include <cuda_bf16.h>
#include <math.h>
#include <cstdint>

// Problem constants
#define Nn 4
#define Cc 64
#define Hh 128
#define Ww 128
#define HW (Hh*Ww)           // 16384
#define Kk 9
#define COUT 64
#define CK (Cc*Kk)           // 576
#define OFFCH 18
#define MASKCH 9
#define OMPAD 32             // 27 offset/mask channels padded to 32

// Scratch (device globals -- allocation-free per harness rules)
__device__ float g_off [Nn*OFFCH*HW];          // offsets [n][18][pq]
__device__ float g_mask[Nn*MASKCH*HW];         // sigmoid(mask) [n][9][pq]
__device__ unsigned short g_whi[Kk*COUT*Cc];   // w_dcn k-major bf16 hi [k][o][c]
__device__ unsigned short g_wlo[Kk*COUT*Cc];
__device__ unsigned short g_omhi[Kk*OMPAD*Cc]; // w_om k-major bf16 hi [k][o:32][c]
__device__ unsigned short g_omlo[Kk*OMPAD*Cc];

// ---------------------------------------------------------------------------
// Warp-MMA helpers (sm_80+ PTX: assembles for target sm_100)
// ---------------------------------------------------------------------------
__device__ __forceinline__ uint32_t smem_u32(const void* p) {
    uint32_t a;
    asm("{ .reg .u64 t; cvta.to.shared.u64 t, %1; cvt.u32.u64 %0, t; }"
        : "=r"(a) : "l"(p));
    return a;
}
__device__ __forceinline__ void ldsm_x4(uint32_t* r, uint32_t addr) {
    asm volatile("ldmatrix.sync.aligned.m8n8.x4.shared.b16 {%0,%1,%2,%3}, [%4];"
        : "=r"(r[0]), "=r"(r[1]), "=r"(r[2]), "=r"(r[3]) : "r"(addr));
}
__device__ __forceinline__ void mma_bf16(float* c, const uint32_t* a, const uint32_t* b) {
    asm volatile(
        "mma.sync.aligned.m16n8k16.row.col.f32.bf16.bf16.f32 "
        "{%0,%1,%2,%3}, {%4,%5,%6,%7}, {%8,%9}, {%0,%1,%2,%3};"
        : "+f"(c[0]), "+f"(c[1]), "+f"(c[2]), "+f"(c[3])
        : "r"(a[0]), "r"(a[1]), "r"(a[2]), "r"(a[3]), "r"(b[0]), "r"(b[1]));
}
__device__ __forceinline__ void split_pack(float v0, float v1,
                                           uint32_t& hi2, uint32_t& lo2) {
    const __nv_bfloat16 h0 = __float2bfloat16(v0);
    const __nv_bfloat16 h1 = __float2bfloat16(v1);
    const uint32_t l0 = __bfloat16_as_ushort(__float2bfloat16(v0 - __bfloat162float(h0)));
    const uint32_t l1 = __bfloat16_as_ushort(__float2bfloat16(v1 - __bfloat162float(h1)));
    hi2 = (uint32_t)__bfloat16_as_ushort(h0) | ((uint32_t)__bfloat16_as_ushort(h1) << 16);
    lo2 = l0 | (l1 << 16);
}

// SMEM layout for fusedBC (dynamic). Row pitch 144B = 128B + 16B skew.
#define PITCH 144
#define SM_DI  0                        // int4[128]
#define SM_DW  (SM_DI + 2048)           // float4[128]
#define SM_SHI (SM_DW + 2048)           // 128*144
#define SM_SLO (SM_SHI + 128*PITCH)
#define SM_WHI (SM_SLO + 128*PITCH)     // 64*144
#define SM_WLO (SM_WHI + 64*PITCH)
#define SM_TOTAL (SM_WLO + 64*PITCH)    // 59392 bytes -> 3 CTAs/SM

// ---------------------------------------------------------------------------
// Kernel W-prep: k-major bf16 hi/lo for BOTH w_dcn and w_om (o-padded to 32)
// ---------------------------------------------------------------------------
#define WPREP_DCN (Kk*COUT*Cc)    // 36864
#define WPREP_TOT (WPREP_DCN + Kk*OMPAD*Cc)  // +18432 = 55296
__global__ __launch_bounds__(256) void wprep_kernel(
    const float* __restrict__ w_dcn, const float* __restrict__ w_om)
{
    const int e = blockIdx.x * 256 + threadIdx.x;
    if (e >= WPREP_TOT) return;
    if (e < WPREP_DCN) {
        const int k = e / (COUT * Cc);
        const int r = e - k * (COUT * Cc);
        const int o = r >> 6;
        const int c = r & 63;
        const float w = __ldg(w_dcn + (size_t)o * CK + c * Kk + k);
        const __nv_bfloat16 hi = __float2bfloat16(w);
        g_whi[e] = __bfloat16_as_ushort(hi);
        g_wlo[e] = __bfloat16_as_ushort(__float2bfloat16(w - __bfloat162float(hi)));
    } else {
        const int e2 = e - WPREP_DCN;
        const int k = e2 >> 11;          // /2048
        const int r = e2 & 2047;
        const int o = r >> 6;
        const int c = r & 63;
        float w = 0.f;
        if (o < 27) w = __ldg(w_om + (size_t)o * CK + c * Kk + k);
        const __nv_bfloat16 hi = __float2bfloat16(w);
        g_omhi[e2] = __bfloat16_as_ushort(hi);
        g_omlo[e2] = __bfloat16_as_ushort(__float2bfloat16(w - __bfloat162float(hi)));
    }
}

// ---------------------------------------------------------------------------
// Kernel A (HMMA): offset/mask conv as GEMM.
//   D[128px, 32o] = sum_k Xtap_k[128, 64] x Wom_k[32, 64]^T, 3-term bf16 split.
//   One block per (image row p, n). Epilogue: bias (+sigmoid) -> g_off/g_mask.
// ---------------------------------------------------------------------------
#define CPITCH 144
__global__ __launch_bounds__(256, 3) void convA_mma_kernel(
    const float* __restrict__ x,
    const float* __restrict__ b_om)
{
    __shared__ char csm[128 * CPITCH * 2 + 32 * CPITCH * 2];  // 46080 B
#define CSHI 0
#define CSLO (128 * CPITCH)
#define CWHI (2 * 128 * CPITCH)
#define CWLO (2 * 128 * CPITCH + 32 * CPITCH)
    const uint32_t sbase = smem_u32(csm);
    const int n   = blockIdx.z;
    const int p   = blockIdx.x;           // image row
    const int tid = threadIdx.x;
    const int wid = tid >> 5;
    const int lid = tid & 31;

    const float* xn = x + (size_t)n * Cc * HW;

    float acc[4][4];
#pragma unroll
    for (int t = 0; t < 4; t++)
#pragma unroll
        for (int i = 0; i < 4; i++) acc[t][i] = 0.f;

    const int a_row  = wid * 16 + (((lid >> 3) & 1) << 3) + (lid & 7);
    const int a_cg   = (lid >> 4);
    const int b_oofs = ((lid >> 4) << 3) + (lid & 7);
    const int b_cg   = ((lid >> 3) & 1);

    const int g_row  = tid & 127;         // pixel (= image column q)
    const int g_half = tid >> 7;          // channel half

    for (int j = 0; j < 9; j++) {
        __syncthreads();

        // Stage W chunk: 1024 u32 per buffer, all 256 threads
        {
            const uint32_t* whp = (const uint32_t*)g_omhi + j * 1024;
            const uint32_t* wlp = (const uint32_t*)g_omlo + j * 1024;
#pragma unroll
            for (int i = 0; i < 4; i++) {
                const int e  = tid + i * 256;      // 0..1023
                const int o  = e >> 5;
                const int cg = e & 31;
                const uint32_t off = o * CPITCH + cg * 4;
                *(uint32_t*)(csm + CWHI + off) = __ldg(whp + e);
                *(uint32_t*)(csm + CWLO + off) = __ldg(wlp + e);
            }
        }
        // Load A chunk: shifted x row (tap j), zero-padded
        {
            const int y  = p + j / 3 - 1;
            const int xc = g_row + j % 3 - 1;
            const bool ok = ((unsigned)y < (unsigned)Hh) & ((unsigned)xc < (unsigned)Ww);
            const float* bp = xn + (size_t)g_half * 32 * HW + y * Ww + xc;
            uint32_t soff = g_row * CPITCH + (g_half * 16) * 4;
#pragma unroll
            for (int i = 0; i < 16; i++) {
                const float v0 = ok ? __ldg(bp)      : 0.f;
                const float v1 = ok ? __ldg(bp + HW) : 0.f;
                bp += 2 * HW;
                uint32_t hi2, lo2;
                split_pack(v0, v1, hi2, lo2);
                *(uint32_t*)(csm + CSHI + soff) = hi2;
                *(uint32_t*)(csm + CSLO + soff) = lo2;
                soff += 4;
            }
        }
        __syncthreads();

#pragma unroll
        for (int ks = 0; ks < 4; ks++) {
            uint32_t ahi[4], alo[4];
            const uint32_t aoff = a_row * CPITCH + (ks * 2 + a_cg) * 16;
            ldsm_x4(ahi, sbase + CSHI + aoff);
            ldsm_x4(alo, sbase + CSLO + aoff);
#pragma unroll
            for (int nt = 0; nt < 2; nt++) {
                uint32_t bh[4], bl[4];
                const uint32_t boff = (nt * 16 + b_oofs) * CPITCH + (ks * 2 + b_cg) * 16;
                ldsm_x4(bh, sbase + CWHI + boff);
                ldsm_x4(bl, sbase + CWLO + boff);
                mma_bf16(acc[nt * 2],     ahi, bh);
                mma_bf16(acc[nt * 2 + 1], ahi, bh + 2);
                mma_bf16(acc[nt * 2],     ahi, bl);
                mma_bf16(acc[nt * 2 + 1], ahi, bl + 2);
                mma_bf16(acc[nt * 2],     alo, bh);
                mma_bf16(acc[nt * 2 + 1], alo, bh + 2);
            }
        }
    }

    // Epilogue: bias, sigmoid on mask ch, scatter to g_off/g_mask
    const int px = p * Ww + wid * 16 + (lid >> 2);
    float* offp = g_off  + (size_t)n * OFFCH  * HW;
    float* mskp = g_mask + (size_t)n * MASKCH * HW;
#pragma unroll
    for (int t = 0; t < 4; t++) {
        const int o0 = t * 8 + 2 * (lid & 3);
#pragma unroll
        for (int i = 0; i < 4; i++) {
            const int o  = o0 + (i & 1);
            const int pq = px + (i >> 1) * 8;
            if (o >= 27) continue;
            const float v = acc[t][i] + __ldg(b_om + o);
            if (o < OFFCH) offp[(size_t)o * HW + pq] = v;
            else           mskp[(size_t)(o - OFFCH) * HW + pq] = 1.f / (1.f + expf(-v));
        }
    }
}

// ---------------------------------------------------------------------------
// Kernel BC: fused deform-sample + HMMA GEMM (unchanged from round 6)
// ---------------------------------------------------------------------------
__global__ __launch_bounds__(256, 3) void fusedBC_mma_kernel(
    const float* __restrict__ x,
    float* __restrict__ out)
{
    extern __shared__ char smem[];
    const uint32_t sbase = smem_u32(smem);
    const int n   = blockIdx.z;
    const int j0  = blockIdx.x * 128;
    const int tid = threadIdx.x;
    const int wid = tid >> 5;
    const int lid = tid & 31;

    int4*   sDI = (int4*)  (smem + SM_DI);
    float4* sDW = (float4*)(smem + SM_DW);

    const float* xn = x + (size_t)n * Cc * HW;

    float acc[8][4];
#pragma unroll
    for (int t = 0; t < 8; t++)
#pragma unroll
        for (int i = 0; i < 4; i++) acc[t][i] = 0.f;

    const int a_row  = wid * 16 + (((lid >> 3) & 1) << 3) + (lid & 7);
    const int a_cg   = (lid >> 4);
    const int b_oofs = ((lid >> 4) << 3) + (lid & 7);
    const int b_cg   = ((lid >> 3) & 1);

    const int g_row  = tid & 127;
    const int g_half = tid >> 7;

    for (int j = 0; j < 9; j++) {
        __syncthreads();

        if (tid < 128) {
            const int row = tid;
            const int pq  = j0 + row;
            const int p   = pq >> 7;
            const int q   = pq & (Ww - 1);

            const float offy = g_off[((size_t)n * OFFCH + 2 * j)     * HW + pq];
            const float offx = g_off[((size_t)n * OFFCH + 2 * j + 1) * HW + pq];
            const float msk  = g_mask[((size_t)n * MASKCH + j) * HW + pq];

            const float y  = (float)(p - 1 + j / 3) + offy;
            const float xs = (float)(q - 1 + j % 3) + offx;

            const float y0f = floorf(y), x0f = floorf(xs);
            const float wy1 = y - y0f,   wx1 = xs - x0f;
            const int   y0 = (int)y0f,   x0 = (int)x0f;
            const int   y1 = y0 + 1,     x1 = x0 + 1;

            float w00 = (1.f - wy1) * (1.f - wx1) * msk;
            float w01 = (1.f - wy1) * wx1 * msk;
            float w10 = wy1 * (1.f - wx1) * msk;
            float w11 = wy1 * wx1 * msk;

            if (!(((unsigned)y0 < (unsigned)Hh) & ((unsigned)x0 < (unsigned)Ww))) w00 = 0.f;
            if (!(((unsigned)y0 < (unsigned)Hh) & ((unsigned)x1 < (unsigned)Ww))) w01 = 0.f;
            if (!(((unsigned)y1 < (unsigned)Hh) & ((unsigned)x0 < (unsigned)Ww))) w10 = 0.f;
            if (!(((unsigned)y1 < (unsigned)Hh) & ((unsigned)x1 < (unsigned)Ww))) w11 = 0.f;

            const int y0c = min(max(y0, 0), Hh - 1);
            const int y1c = min(max(y1, 0), Hh - 1);
            const int x0c = min(max(x0, 0), Ww - 1);
            const int x1c = min(max(x1, 0), Ww - 1);

            sDI[row] = make_int4(y0c * Ww + x0c, y0c * Ww + x1c,
                                 y1c * Ww + x0c, y1c * Ww + x1c);
            sDW[row] = make_float4(w00, w01, w10, w11);
        } else {
            const uint32_t* whp = (const uint32_t*)g_whi + j * 2048;
            const uint32_t* wlp = (const uint32_t*)g_wlo + j * 2048;
#pragma unroll 4
            for (int i = 0; i < 16; i++) {
                const int e  = (tid - 128) + i * 128;
                const int o  = e >> 5;
                const int cg = e & 31;
                const uint32_t off = o * PITCH + cg * 4;
                *(uint32_t*)(smem + SM_WHI + off) = __ldg(whp + e);
                *(uint32_t*)(smem + SM_WLO + off) = __ldg(wlp + e);
            }
        }
        __syncthreads();

        {
            const int4   ii = sDI[g_row];
            const float4 wv = sDW[g_row];
            const float* p00 = xn + ii.x + (size_t)g_half * 32 * HW;
            const float* p01 = xn + ii.y + (size_t)g_half * 32 * HW;
            const float* p10 = xn + ii.z + (size_t)g_half * 32 * HW;
            const float* p11 = xn + ii.w + (size_t)g_half * 32 * HW;
            uint32_t soff = g_row * PITCH + (g_half * 16) * 4;
#pragma unroll
            for (int i = 0; i < 16; i++) {
                float v0 = wv.x * __ldg(p00)      + wv.y * __ldg(p01)
                         + wv.z * __ldg(p10)      + wv.w * __ldg(p11);
                float v1 = wv.x * __ldg(p00 + HW) + wv.y * __ldg(p01 + HW)
                         + wv.z * __ldg(p10 + HW) + wv.w * __ldg(p11 + HW);
                p00 += 2 * HW; p01 += 2 * HW; p10 += 2 * HW; p11 += 2 * HW;
                uint32_t hi2, lo2;
                split_pack(v0, v1, hi2, lo2);
                *(uint32_t*)(smem + SM_SHI + soff) = hi2;
                *(uint32_t*)(smem + SM_SLO + soff) = lo2;
                soff += 4;
            }
        }
        __syncthreads();

#pragma unroll
        for (int ks = 0; ks < 4; ks++) {
            uint32_t ahi[4], alo[4];
            const uint32_t aoff = a_row * PITCH + (ks * 2 + a_cg) * 16;
            ldsm_x4(ahi, sbase + SM_SHI + aoff);
            ldsm_x4(alo, sbase + SM_SLO + aoff);
#pragma unroll
            for (int nt = 0; nt < 4; nt++) {
                uint32_t bh[4], bl[4];
                const uint32_t boff = (nt * 16 + b_oofs) * PITCH + (ks * 2 + b_cg) * 16;
                ldsm_x4(bh, sbase + SM_WHI + boff);
                ldsm_x4(bl, sbase + SM_WLO + boff);
                mma_bf16(acc[nt * 2],     ahi, bh);
                mma_bf16(acc[nt * 2 + 1], ahi, bh + 2);
                mma_bf16(acc[nt * 2],     ahi, bl);
                mma_bf16(acc[nt * 2 + 1], ahi, bl + 2);
                mma_bf16(acc[nt * 2],     alo, bh);
                mma_bf16(acc[nt * 2 + 1], alo, bh + 2);
            }
        }
    }

    const int px = j0 + wid * 16 + (lid >> 2);
    float* op = out + (size_t)n * COUT * HW;
#pragma unroll
    for (int t = 0; t < 8; t++) {
        const int o0 = t * 8 + 2 * (lid & 3);
        op[(size_t)o0       * HW + px    ] = acc[t][0];
        op[(size_t)(o0 + 1) * HW + px    ] = acc[t][1];
        op[(size_t)o0       * HW + px + 8] = acc[t][2];
        op[(size_t)(o0 + 1) * HW + px + 8] = acc[t][3];
    }
}

// ---------------------------------------------------------------------------
extern "C" void kernel_launch(void* const* d_in, const int* in_sizes, int n_in,
                              void* d_out, int out_size)
{
    const float* x     = (const float*)d_in[0];  // (4,64,128,128)
    const float* w_om  = (const float*)d_in[1];  // (27,64,3,3)
    const float* b_om  = (const float*)d_in[2];  // (27,)
    const float* w_dcn = (const float*)d_in[3];  // (64,64,3,3)
    float* out = (float*)d_out;                  // (4,64,128,128)

    wprep_kernel<<<(WPREP_TOT + 255) / 256, 256>>>(w_dcn, w_om);

    dim3 gA(Hh, 1, Nn);                          // 128 x 4 = 512 blocks
    convA_mma_kernel<<<gA, 256>>>(x, b_om);

    cudaFuncSetAttribute(fusedBC_mma_kernel,
                         cudaFuncAttributeMaxDynamicSharedMemorySize, SM_TOTAL);
    dim3 gBC(HW / 128, 1, Nn);                   // 512 blocks
    fusedBC_mma_kernel<<<gBC, 256, SM_TOTAL>>>(x, out);
}